// round 16
// baseline (speedup 1.0000x reference)
#include <cuda_runtime.h>
#include <cstdint>

// Problem constants (fixed by setup_inputs)
#define BS 8
#define M  4096
#define T  32
#define E  65536
#define NROWS (BS * M)          // 32768
#define DEG_CAP 64              // Poisson(16) row degree; P(>64) ~ 1e-20

// Scratch. Device globals start zeroed at module load; agg resets the header
// counts after consuming them, so every replay starts clean. Stale entry
// bytes are never read as live data (keep-mask bits beyond deg are zero) and
// are always < M, so gathers stay in-bounds.
//
// Per-row 16B header: {u32 cnt; u16 e0,e1,e2,e3; 4B pad} -> one LDG.128 in
// agg yields count + the whole fast-path quad. Entries pos >= 4 go to the
// overflow array at [row*64 + pos] (first 4 slots of each ovf row unused).
__device__ uint4   g_rec[NROWS];                 // headers (512 KB)
__device__ ushort4 g_ovf[NROWS * (DEG_CAP / 4)]; // overflow lists (4 MB)

__device__ __forceinline__ void add4(float4& a, const float4& v) {
    a.x += v.x; a.y += v.y; a.z += v.z; a.w += v.w;
}

// ---------------------------------------------------------------------------
// Kernel 1: append every edge (dups included -> dedup lazily in agg). ONE
// atomic per edge, 2 edges per thread (independent chains, MLP=2).
// A_coo is int32, layout (bs, 2, E) row-major; int2 loads from both streams.
// ---------------------------------------------------------------------------
__global__ void nil_build_kernel(const int* __restrict__ coo,
                                 float* __restrict__ out) {
    unsigned tid = blockIdx.x * blockDim.x + threadIdx.x;  // < BS*E/2
    if (tid == 0) *out = 0.0f;
    unsigned b  = tid >> 15;               // / (E/2)
    unsigned e2 = tid & (E / 2 - 1);       // edge-pair index within batch

    const int2* srcs = reinterpret_cast<const int2*>(coo + (size_t)b * 2 * E);
    const int2* tgts = reinterpret_cast<const int2*>(coo + (size_t)b * 2 * E + E);
    int2 sp = srcs[e2];
    int2 tp = tgts[e2];

    unsigned* cnts = reinterpret_cast<unsigned*>(g_rec);  // cnt @ idx row*4
    unsigned short* hdr = reinterpret_cast<unsigned short*>(g_rec);
    unsigned short* ovf = reinterpret_cast<unsigned short*>(g_ovf);

    unsigned src[2] = {(unsigned)sp.x & (M - 1), (unsigned)sp.y & (M - 1)};
    unsigned tgt[2] = {(unsigned)tp.x & (M - 1), (unsigned)tp.y & (M - 1)};
    unsigned row[2] = {b * M + src[0], b * M + src[1]};
    unsigned pos[2];
    #pragma unroll
    for (int p = 0; p < 2; ++p)            // independent chains back-to-back
        pos[p] = atomicAdd(&cnts[row[p] * 4], 1u);
    #pragma unroll
    for (int p = 0; p < 2; ++p) {
        if (pos[p] < 4)
            hdr[row[p] * 8 + 2 + pos[p]] = (unsigned short)tgt[p];
        else if (pos[p] < DEG_CAP)
            ovf[row[p] * DEG_CAP + pos[p]] = (unsigned short)tgt[p];
    }
}

// ---------------------------------------------------------------------------
// Kernel 2: one warp per EIGHT consecutive rows = two independent 4-row
// tiles (a: rows row0..row0+3, b: rows row0+4..row0+7). Lane l = (group
// g=l/8 -> row-in-tile, chunk c=l%8 -> t in [4c,4c+3]) holding acc as float4.
//   acc[t] = yb[b,i,t] (identity) + sum over DISTINCT listed targets j of
//            yb[b,j,t]  (first occurrence wins == jnp .at[].set(1.0))
//   reg   += relu(yb[b,i,t+1] - acc[t]), t in [0,31)
// Fast path: both tiles' header loads, self loads and 8 gathers are fully
// independent (front-batched, MLP=8). Rows with acc >= ynext on all t
// contribute EXACTLY 0 (y >= 0 -> acc monotone). Live rows (~4%) take a
// warp-converged match_any keep-mask slow path with 2-quad early-exit steps.
// ---------------------------------------------------------------------------
__global__ void nil_agg_kernel(const float* __restrict__ y,
                               float* __restrict__ out) {
    const unsigned FULL = 0xffffffffu;
    unsigned warp = (blockIdx.x * blockDim.x + threadIdx.x) >> 5; // 0..4095
    unsigned lane = threadIdx.x & 31;
    unsigned g = lane >> 3, c = lane & 7;

    unsigned row0  = warp << 3;       // 8 consecutive rows, same batch (M%8==0)
    unsigned row_a = row0 + g;
    unsigned row_b = row0 + 4 + g;
    unsigned b     = row0 >> 12;      // / M
    const float*  yb  = y + (size_t)b * (M * T);
    const float4* yb4 = reinterpret_cast<const float4*>(yb);

    // ---- front-issue ALL independent loads (both tiles) ----
    uint4 rec_a = g_rec[row_a];
    uint4 rec_b = g_rec[row_b];
    float4 self_a = yb4[(size_t)(row_a & (M - 1)) * (T / 4) + c];
    float4 self_b = yb4[(size_t)(row_b & (M - 1)) * (T / 4) + c];

    if (lane < 8)                                      // self-clean counts
        reinterpret_cast<unsigned*>(g_rec)[(row0 + lane) * 4] = 0u;

    int deg_a = (int)rec_a.x; if (deg_a > DEG_CAP) deg_a = DEG_CAP;
    int deg_b = (int)rec_b.x; if (deg_b > DEG_CAP) deg_b = DEG_CAP;

    float4 acc_a = self_a;            // identity terms
    float4 acc_b = self_b;
    float n3a = __shfl_down_sync(FULL, self_a.x, 1);  // masked at c==7
    float n3b = __shfl_down_sync(FULL, self_b.x, 1);

    // ---- quad 0 for both tiles: 8 independent LDG.128 per lane ----
    {
        unsigned a0 = rec_a.y & 0xFFFFu, a1 = rec_a.y >> 16;
        unsigned a2 = rec_a.z & 0xFFFFu, a3 = rec_a.z >> 16;
        unsigned b0 = rec_b.y & 0xFFFFu, b1 = rec_b.y >> 16;
        unsigned b2 = rec_b.z & 0xFFFFu, b3 = rec_b.z >> 16;
        float4 va0 = yb4[a0 * (T / 4) + c];
        float4 va1 = yb4[a1 * (T / 4) + c];
        float4 va2 = yb4[a2 * (T / 4) + c];
        float4 va3 = yb4[a3 * (T / 4) + c];
        float4 vb0 = yb4[b0 * (T / 4) + c];
        float4 vb1 = yb4[b1 * (T / 4) + c];
        float4 vb2 = yb4[b2 * (T / 4) + c];
        float4 vb3 = yb4[b3 * (T / 4) + c];
        bool ua1 = (a1 != a0);
        bool ua2 = (a2 != a0) & (a2 != a1);
        bool ua3 = (a3 != a0) & (a3 != a1) & (a3 != a2);
        if (deg_a > 0)        add4(acc_a, va0);
        if (deg_a > 1 && ua1) add4(acc_a, va1);
        if (deg_a > 2 && ua2) add4(acc_a, va2);
        if (deg_a > 3 && ua3) add4(acc_a, va3);
        bool ub1 = (b1 != b0);
        bool ub2 = (b2 != b0) & (b2 != b1);
        bool ub3 = (b3 != b0) & (b3 != b1) & (b3 != b2);
        if (deg_b > 0)        add4(acc_b, vb0);
        if (deg_b > 1 && ub1) add4(acc_b, vb1);
        if (deg_b > 2 && ub2) add4(acc_b, vb2);
        if (deg_b > 3 && ub3) add4(acc_b, vb3);
    }

    // ---- liveness per tile ----
    bool live_a = (acc_a.x < self_a.y) | (acc_a.y < self_a.z) |
                  (acc_a.z < self_a.w) | ((c < 7) & (acc_a.w < n3a));
    bool live_b = (acc_b.x < self_b.y) | (acc_b.y < self_b.z) |
                  (acc_b.z < self_b.w) | ((c < 7) & (acc_b.w < n3b));
    unsigned pend_a = __ballot_sync(FULL, live_a);
    unsigned pend_b = __ballot_sync(FULL, live_b);

    float wsum = 0.0f;                        // meaningful on lane 0 only
    if (pend_a | pend_b) {
        // ---- warp-converged slow path, one live row at a time (rolled to
        //      keep code size small; gg is warp-uniform) ----
        #pragma unroll 1
        for (int gg = 0; gg < 8; ++gg) {
            bool ta = (gg < 4);
            unsigned pp = ta ? pend_a : pend_b;
            if (!((pp >> (8 * (gg & 3))) & 0xFFu)) continue;
            unsigned r_row = row0 + gg;
            unsigned srcw = (gg & 3) * 8;
            int dg = __shfl_sync(FULL, ta ? deg_a : deg_b, srcw);
            unsigned w1 = __shfl_sync(FULL, ta ? rec_a.y : rec_b.y, srcw);
            unsigned w2 = __shfl_sync(FULL, ta ? rec_a.z : rec_b.z, srcw);

            // transpose this row's acc AND self into lane=t layout (regs only)
            unsigned srcl = srcw + (lane >> 2);
            float a0 = __shfl_sync(FULL, ta ? acc_a.x : acc_b.x, srcl);
            float a1 = __shfl_sync(FULL, ta ? acc_a.y : acc_b.y, srcl);
            float a2 = __shfl_sync(FULL, ta ? acc_a.z : acc_b.z, srcl);
            float a3 = __shfl_sync(FULL, ta ? acc_a.w : acc_b.w, srcl);
            float s0 = __shfl_sync(FULL, ta ? self_a.x : self_b.x, srcl);
            float s1 = __shfl_sync(FULL, ta ? self_a.y : self_b.y, srcl);
            float s2 = __shfl_sync(FULL, ta ? self_a.z : self_b.z, srcl);
            float s3 = __shfl_sync(FULL, ta ? self_a.w : self_b.w, srcl);
            unsigned sel = lane & 3;
            float accT  = (sel == 0) ? a0 : (sel == 1) ? a1
                        : (sel == 2) ? a2 : a3;
            float selfT = (sel == 0) ? s0 : (sel == 1) ? s1
                        : (sel == 2) ? s2 : s3;
            float ynT = __shfl_down_sync(FULL, selfT, 1);
            bool tv = (lane < 31);

            const unsigned short* ovf =
                reinterpret_cast<const unsigned short*>(g_ovf) +
                (size_t)r_row * DEG_CAP;
            const ushort4* l4 = g_ovf + (size_t)r_row * (DEG_CAP / 4);

            // lane-owned entries: 0-3 from header words, 4..31 from overflow
            unsigned hdr_e = (lane < 2) ? ((lane & 1) ? (w1 >> 16) : (w1 & 0xFFFFu))
                                        : ((lane & 1) ? (w2 >> 16) : (w2 & 0xFFFFu));
            unsigned e_lo = (lane < (unsigned)dg)
                                ? ((lane < 4) ? hdr_e : (unsigned)ovf[lane])
                                : (0x10000u | lane);
            unsigned m_lo = __match_any_sync(FULL, e_lo);
            bool k_lo = (lane < (unsigned)dg) &&
                        ((m_lo & ((1u << lane) - 1u)) == 0u);
            unsigned long long keep =
                (unsigned long long)__ballot_sync(FULL, k_lo);
            if (dg > 32) {                    // warp-uniform, P ~ 1e-4
                unsigned e_hi = (lane + 32 < (unsigned)dg)
                                    ? (unsigned)ovf[lane + 32]
                                    : (0x20000u | lane);
                unsigned m_hi = __match_any_sync(FULL, e_hi);
                bool k_hi = (lane + 32 < (unsigned)dg) &&
                            ((m_hi & ((1u << lane) - 1u)) == 0u);
                bool dup = false;             // cross-half duplicate test
                #pragma unroll
                for (int l = 0; l < 32; ++l) {
                    unsigned v = __shfl_sync(FULL, e_lo, l);
                    dup = dup || (v == e_hi);
                }
                k_hi = k_hi && !dup;
                keep |= ((unsigned long long)__ballot_sync(FULL, k_hi)) << 32;
            }

            // ---- TWO quads (8 entries) per early-exit check; keep bits
            //      beyond dg are zero so no per-element bounds checks ----
            unsigned pnd = __ballot_sync(FULL, tv && accT < ynT);
            for (int k = 4; k < dg && pnd; k += 8) {
                unsigned qa_i = (unsigned)(k >> 2);
                unsigned qb_i = qa_i + 1u;
                if (qb_i > 15u) qb_i = 15u;   // clamp: stay inside this row
                ushort4 qa = l4[qa_i];
                ushort4 qb = l4[qb_i];
                float g0 = yb[(size_t)qa.x * T + lane];
                float g1 = yb[(size_t)qa.y * T + lane];
                float g2 = yb[(size_t)qa.z * T + lane];
                float g3 = yb[(size_t)qa.w * T + lane];
                float g4 = yb[(size_t)qb.x * T + lane];
                float g5 = yb[(size_t)qb.y * T + lane];
                float g6 = yb[(size_t)qb.z * T + lane];
                float g7 = yb[(size_t)qb.w * T + lane];
                unsigned kb = (unsigned)(keep >> k) & 0xFFu;  // warp-uniform
                if (kb & 0x01u) accT += g0;
                if (kb & 0x02u) accT += g1;
                if (kb & 0x04u) accT += g2;
                if (kb & 0x08u) accT += g3;
                if (kb & 0x10u) accT += g4;
                if (kb & 0x20u) accT += g5;
                if (kb & 0x40u) accT += g6;
                if (kb & 0x80u) accT += g7;
                pnd = __ballot_sync(FULL, tv && accT < ynT);
            }
            if (pnd) {
                float rr = tv ? fmaxf(ynT - accT, 0.0f) : 0.0f;
                #pragma unroll
                for (int o = 16; o > 0; o >>= 1)
                    rr += __shfl_down_sync(FULL, rr, o);
                wsum += rr;                   // total lands on lane 0
            }
        }
    }

    // block reduce (8 warps/block) -> at most one atomic per block
    __shared__ float sred[8];
    unsigned wib = threadIdx.x >> 5;
    if (lane == 0) sred[wib] = wsum;
    __syncthreads();
    if (threadIdx.x < 8) {
        float v = sred[threadIdx.x];
        #pragma unroll
        for (int o = 4; o > 0; o >>= 1)
            v += __shfl_down_sync(0x000000ffu, v, o);
        if (threadIdx.x == 0 && v != 0.0f) atomicAdd(out, v);
    }
}

// ---------------------------------------------------------------------------
// kernel_launch: build -> aggregate. Plain launches, no allocs/syncs.
// ---------------------------------------------------------------------------
extern "C" void kernel_launch(void* const* d_in, const int* in_sizes, int n_in,
                              void* d_out, int out_size) {
    (void)in_sizes; (void)n_in; (void)out_size;
    const float* y   = (const float*)d_in[0];
    const int*   coo = (const int*)d_in[1];
    float*       out = (float*)d_out;

    nil_build_kernel<<<(BS * E / 2) / 256, 256>>>(coo, out);
    // 32768 rows / 8 rows per warp / 8 warps per block = 512 blocks
    nil_agg_kernel<<<NROWS / 64, 256>>>(y, out);
}

// round 17
// speedup vs baseline: 1.0935x; 1.0935x over previous
#include <cuda_runtime.h>
#include <cstdint>

// Problem constants (fixed by setup_inputs)
#define BS 8
#define M  4096
#define T  32
#define E  65536
#define NROWS (BS * M)          // 32768
#define DEG_CAP 64              // Poisson(16) row degree; P(>64) ~ 1e-20

// Scratch. Device globals start zeroed at module load; agg resets the header
// counts after consuming them, so every replay starts clean. Stale entry
// bytes are never read as live data (adds are deg-predicated / keep-mask bits
// beyond deg are zero) and are always < M, so gathers stay in-bounds.
//
// Per-row 16B header: {u32 cnt; u16 e0,e1,e2,e3; 4B pad} -> one LDG.128 in
// agg yields count + the first quad. Entries pos >= 4 go to the overflow
// array at [row*64 + pos] (first 4 slots of each ovf row unused).
__device__ uint4   g_rec[NROWS];                 // headers (512 KB)
__device__ ushort4 g_ovf[NROWS * (DEG_CAP / 4)]; // overflow lists (4 MB)

__device__ __forceinline__ void add4(float4& a, const float4& v) {
    a.x += v.x; a.y += v.y; a.z += v.z; a.w += v.w;
}

// ---------------------------------------------------------------------------
// Kernel 1: append every edge (dups included -> dedup lazily in agg). ONE
// atomic per edge, 2 edges per thread (independent chains, MLP=2).
// A_coo is int32, layout (bs, 2, E) row-major; int2 loads from both streams.
// ---------------------------------------------------------------------------
__global__ void nil_build_kernel(const int* __restrict__ coo,
                                 float* __restrict__ out) {
    unsigned tid = blockIdx.x * blockDim.x + threadIdx.x;  // < BS*E/2
    if (tid == 0) *out = 0.0f;
    unsigned b  = tid >> 15;               // / (E/2)
    unsigned e2 = tid & (E / 2 - 1);       // edge-pair index within batch

    const int2* srcs = reinterpret_cast<const int2*>(coo + (size_t)b * 2 * E);
    const int2* tgts = reinterpret_cast<const int2*>(coo + (size_t)b * 2 * E + E);
    int2 sp = srcs[e2];
    int2 tp = tgts[e2];

    unsigned* cnts = reinterpret_cast<unsigned*>(g_rec);  // cnt @ idx row*4
    unsigned short* hdr = reinterpret_cast<unsigned short*>(g_rec);
    unsigned short* ovf = reinterpret_cast<unsigned short*>(g_ovf);

    unsigned src[2] = {(unsigned)sp.x & (M - 1), (unsigned)sp.y & (M - 1)};
    unsigned tgt[2] = {(unsigned)tp.x & (M - 1), (unsigned)tp.y & (M - 1)};
    unsigned row[2] = {b * M + src[0], b * M + src[1]};
    unsigned pos[2];
    #pragma unroll
    for (int p = 0; p < 2; ++p)            // independent chains back-to-back
        pos[p] = atomicAdd(&cnts[row[p] * 4], 1u);
    #pragma unroll
    for (int p = 0; p < 2; ++p) {
        if (pos[p] < 4)
            hdr[row[p] * 8 + 2 + pos[p]] = (unsigned short)tgt[p];
        else if (pos[p] < DEG_CAP)
            ovf[row[p] * DEG_CAP + pos[p]] = (unsigned short)tgt[p];
    }
}

// ---------------------------------------------------------------------------
// Kernel 2: one warp per FOUR consecutive rows. Lane l = (group g=l/8 -> row
// 4w+g, chunk c=l%8 -> t in [4c,4c+3]) holding acc as float4.
//   acc[t] = yb[b,i,t] (identity) + sum over DISTINCT listed targets j of
//            yb[b,j,t]  (first occurrence wins == jnp .at[].set(1.0))
//   reg   += relu(yb[b,i,t+1] - acc[t]), t in [0,31)
// Fast path: header (16B) + overflow quad 1 (8B, independent address) give
// the first EIGHT entries; 8 parallel gathers + pairwise register dedup.
// With identity + 8 neighbors, P(row still live) ~ 31/10! -> the slow path
// runs for ~0.5% of rows (mostly deg<8), killing the straggler tail.
// Rows with acc >= ynext on all t contribute EXACTLY 0 (y >= 0 -> acc
// monotone). Live rows take the warp-converged match_any keep-mask slow path
// (2-quad early-exit steps, starting at entry 8).
// ---------------------------------------------------------------------------
__global__ void nil_agg_kernel(const float* __restrict__ y,
                               float* __restrict__ out) {
    const unsigned FULL = 0xffffffffu;
    unsigned warp = (blockIdx.x * blockDim.x + threadIdx.x) >> 5; // 0..8191
    unsigned lane = threadIdx.x & 31;
    unsigned g = lane >> 3, c = lane & 7;

    unsigned row0 = warp << 2;        // 4 consecutive rows, same batch (M%4==0)
    unsigned row  = row0 + g;
    unsigned b    = row0 >> 12;       // / M
    const float*  yb  = y + (size_t)b * (M * T);
    const float4* yb4 = reinterpret_cast<const float4*>(yb);

    // ---- front-issue independent loads (header / ovf quad 1 / self) ----
    uint4 rec = g_rec[row];                              // 16B header
    ushort4 q1 = g_ovf[(size_t)row * (DEG_CAP / 4) + 1]; // entries 4..7
    float4 self4 = yb4[(size_t)(row & (M - 1)) * (T / 4) + c]; // 512B/warp

    if (lane < 4)                                        // self-clean counts
        reinterpret_cast<unsigned*>(g_rec)[(row0 + lane) * 4] = 0u;

    int deg = (int)rec.x;
    if (deg > DEG_CAP) deg = DEG_CAP;

    float4 acc = self4;                       // identity term
    // ynext for t=4c..4c+3: (self.y, self.z, self.w, next-lane self.x);
    // c==7's 4th term (t=31) is invalid and masked below.
    float n3 = __shfl_down_sync(FULL, self4.x, 1);

    // ---- entries 0..7: 8 parallel gathers + pairwise first-occurrence
    //      dedup (identical semantics to the match_any keep mask) ----
    {
        unsigned e0 = rec.y & 0xFFFFu, e1 = rec.y >> 16;
        unsigned e2 = rec.z & 0xFFFFu, e3 = rec.z >> 16;
        unsigned e4 = q1.x, e5 = q1.y, e6 = q1.z, e7 = q1.w;
        float4 v0 = yb4[e0 * (T / 4) + c];
        float4 v1 = yb4[e1 * (T / 4) + c];
        float4 v2 = yb4[e2 * (T / 4) + c];
        float4 v3 = yb4[e3 * (T / 4) + c];
        float4 v4 = yb4[e4 * (T / 4) + c];
        float4 v5 = yb4[e5 * (T / 4) + c];
        float4 v6 = yb4[e6 * (T / 4) + c];
        float4 v7 = yb4[e7 * (T / 4) + c];
        bool u1 = (e1 != e0);
        bool u2 = (e2 != e0) & (e2 != e1);
        bool u3 = (e3 != e0) & (e3 != e1) & (e3 != e2);
        bool u4 = (e4 != e0) & (e4 != e1) & (e4 != e2) & (e4 != e3);
        bool u5 = (e5 != e0) & (e5 != e1) & (e5 != e2) & (e5 != e3) &
                  (e5 != e4);
        bool u6 = (e6 != e0) & (e6 != e1) & (e6 != e2) & (e6 != e3) &
                  (e6 != e4) & (e6 != e5);
        bool u7 = (e7 != e0) & (e7 != e1) & (e7 != e2) & (e7 != e3) &
                  (e7 != e4) & (e7 != e5) & (e7 != e6);
        if (deg > 0)       add4(acc, v0);
        if (deg > 1 && u1) add4(acc, v1);
        if (deg > 2 && u2) add4(acc, v2);
        if (deg > 3 && u3) add4(acc, v3);
        if (deg > 4 && u4) add4(acc, v4);
        if (deg > 5 && u5) add4(acc, v5);
        if (deg > 6 && u6) add4(acc, v6);
        if (deg > 7 && u7) add4(acc, v7);
    }

    // ---- liveness: any t in this lane with acc[t] < ynext[t]? ----
    bool live = (acc.x < self4.y) | (acc.y < self4.z) | (acc.z < self4.w) |
                ((c < 7) & (acc.w < n3));
    unsigned pend = __ballot_sync(FULL, live);

    float wsum = 0.0f;                        // meaningful on lane 0 only
    if (pend) {
        // ---- warp-converged slow path, one live row at a time ----
        #pragma unroll 1
        for (int gg = 0; gg < 4; ++gg) {
            if (!((pend >> (8 * gg)) & 0xFFu)) continue;
            unsigned r_row = row0 + gg;
            unsigned srcw = gg * 8;
            int dg = __shfl_sync(FULL, deg, srcw);
            unsigned w1 = __shfl_sync(FULL, rec.y, srcw);
            unsigned w2 = __shfl_sync(FULL, rec.z, srcw);

            // transpose this row's acc AND self into lane=t layout (regs only)
            unsigned srcl = srcw + (lane >> 2);
            float a0 = __shfl_sync(FULL, acc.x, srcl);
            float a1 = __shfl_sync(FULL, acc.y, srcl);
            float a2 = __shfl_sync(FULL, acc.z, srcl);
            float a3 = __shfl_sync(FULL, acc.w, srcl);
            float s0 = __shfl_sync(FULL, self4.x, srcl);
            float s1 = __shfl_sync(FULL, self4.y, srcl);
            float s2 = __shfl_sync(FULL, self4.z, srcl);
            float s3 = __shfl_sync(FULL, self4.w, srcl);
            unsigned sel = lane & 3;
            float accT  = (sel == 0) ? a0 : (sel == 1) ? a1
                        : (sel == 2) ? a2 : a3;
            float selfT = (sel == 0) ? s0 : (sel == 1) ? s1
                        : (sel == 2) ? s2 : s3;
            float ynT = __shfl_down_sync(FULL, selfT, 1);
            bool tv = (lane < 31);

            const unsigned short* ovf =
                reinterpret_cast<const unsigned short*>(g_ovf) +
                (size_t)r_row * DEG_CAP;
            const ushort4* l4 = g_ovf + (size_t)r_row * (DEG_CAP / 4);

            // lane-owned entries: 0-3 from header words, 4..31 from overflow
            unsigned hdr_e = (lane < 2) ? ((lane & 1) ? (w1 >> 16) : (w1 & 0xFFFFu))
                                        : ((lane & 1) ? (w2 >> 16) : (w2 & 0xFFFFu));
            unsigned e_lo = (lane < (unsigned)dg)
                                ? ((lane < 4) ? hdr_e : (unsigned)ovf[lane])
                                : (0x10000u | lane);
            unsigned m_lo = __match_any_sync(FULL, e_lo);
            bool k_lo = (lane < (unsigned)dg) &&
                        ((m_lo & ((1u << lane) - 1u)) == 0u);
            unsigned long long keep =
                (unsigned long long)__ballot_sync(FULL, k_lo);
            if (dg > 32) {                    // warp-uniform, P ~ 1e-4
                unsigned e_hi = (lane + 32 < (unsigned)dg)
                                    ? (unsigned)ovf[lane + 32]
                                    : (0x20000u | lane);
                unsigned m_hi = __match_any_sync(FULL, e_hi);
                bool k_hi = (lane + 32 < (unsigned)dg) &&
                            ((m_hi & ((1u << lane) - 1u)) == 0u);
                bool dup = false;             // cross-half duplicate test
                #pragma unroll
                for (int l = 0; l < 32; ++l) {
                    unsigned v = __shfl_sync(FULL, e_lo, l);
                    dup = dup || (v == e_hi);
                }
                k_hi = k_hi && !dup;
                keep |= ((unsigned long long)__ballot_sync(FULL, k_hi)) << 32;
            }

            // ---- TWO quads (8 entries) per early-exit check, starting at
            //      entry 8 (0..7 consumed by the fast path). Keep bits
            //      beyond dg are zero, so no per-element bounds checks. ----
            unsigned pnd = __ballot_sync(FULL, tv && accT < ynT);
            for (int k = 8; k < dg && pnd; k += 8) {
                unsigned qa_i = (unsigned)(k >> 2);
                unsigned qb_i = qa_i + 1u;
                if (qb_i > 15u) qb_i = 15u;   // clamp: stay inside this row
                ushort4 qa = l4[qa_i];
                ushort4 qb = l4[qb_i];
                float g0 = yb[(size_t)qa.x * T + lane];
                float g1 = yb[(size_t)qa.y * T + lane];
                float g2 = yb[(size_t)qa.z * T + lane];
                float g3 = yb[(size_t)qa.w * T + lane];
                float g4 = yb[(size_t)qb.x * T + lane];
                float g5 = yb[(size_t)qb.y * T + lane];
                float g6 = yb[(size_t)qb.z * T + lane];
                float g7 = yb[(size_t)qb.w * T + lane];
                unsigned kb = (unsigned)(keep >> k) & 0xFFu;  // warp-uniform
                if (kb & 0x01u) accT += g0;
                if (kb & 0x02u) accT += g1;
                if (kb & 0x04u) accT += g2;
                if (kb & 0x08u) accT += g3;
                if (kb & 0x10u) accT += g4;
                if (kb & 0x20u) accT += g5;
                if (kb & 0x40u) accT += g6;
                if (kb & 0x80u) accT += g7;
                pnd = __ballot_sync(FULL, tv && accT < ynT);
            }
            if (pnd) {
                float rr = tv ? fmaxf(ynT - accT, 0.0f) : 0.0f;
                #pragma unroll
                for (int o = 16; o > 0; o >>= 1)
                    rr += __shfl_down_sync(FULL, rr, o);
                wsum += rr;                   // total lands on lane 0
            }
        }
    }

    // block reduce (8 warps/block) -> at most one atomic per block
    __shared__ float sred[8];
    unsigned wib = threadIdx.x >> 5;
    if (lane == 0) sred[wib] = wsum;
    __syncthreads();
    if (threadIdx.x < 8) {
        float v = sred[threadIdx.x];
        #pragma unroll
        for (int o = 4; o > 0; o >>= 1)
            v += __shfl_down_sync(0x000000ffu, v, o);
        if (threadIdx.x == 0 && v != 0.0f) atomicAdd(out, v);
    }
}

// ---------------------------------------------------------------------------
// kernel_launch: build -> aggregate. Plain launches, no allocs/syncs.
// ---------------------------------------------------------------------------
extern "C" void kernel_launch(void* const* d_in, const int* in_sizes, int n_in,
                              void* d_out, int out_size) {
    (void)in_sizes; (void)n_in; (void)out_size;
    const float* y   = (const float*)d_in[0];
    const int*   coo = (const int*)d_in[1];
    float*       out = (float*)d_out;

    nil_build_kernel<<<(BS * E / 2) / 256, 256>>>(coo, out);
    // 32768 rows / 4 rows per warp / 8 warps per block = 1024 blocks
    nil_agg_kernel<<<NROWS / 32, 256>>>(y, out);
}